// round 15
// baseline (speedup 1.0000x reference)
#include <cuda_runtime.h>
#include <cstdint>

// SSIM loss: fused separable 11x11 Gaussian, V-first, interleaved smem planes.
// Channels: blur(x), blur(y), blur(x^2+y^2), blur(xy) -> two packed f32x2.
// 64x16 tiles, NT=192, 8 CTAs/SM (phase mixing) x 48 warps/SM; LEN<=6 H strips.

#define IMG     512
#define NIMG    48
#define TX      64
#define TY      16
#define COLS    74              // TX + 10
#define VP      75              // V plane row stride in ulonglong2 elements
#define NT      192             // 6 warps
#define GXB     8
#define GYB     32
#define NBLOCKS (GXB*GYB*NIMG)  // 12288
#define SMEM_BYTES (TY*VP*16)   // 19200

#define W0f 0.00102838f
#define W1f 0.00759876f
#define W2f 0.03600077f
#define W3f 0.10936070f
#define W4f 0.21300554f
#define W5f 0.26601173f

__device__ float    g_partials[NBLOCKS];
__device__ unsigned g_sync = 0;

__device__ __forceinline__ uint64_t bc(float w) {
    unsigned u = __float_as_uint(w);
    return ((uint64_t)u << 32) | u;
}
__device__ __forceinline__ void f2fma(uint64_t& d, uint64_t a, uint64_t b) {
    asm("fma.rn.f32x2 %0,%1,%2,%0;" : "+l"(d) : "l"(a), "l"(b));
}
__device__ __forceinline__ uint64_t pack2(float lo, float hi) {
    uint64_t r; asm("mov.b64 %0,{%1,%2};" : "=l"(r) : "r"(__float_as_uint(lo)), "r"(__float_as_uint(hi)));
    return r;
}
__device__ __forceinline__ float lo32(uint64_t u) { return __uint_as_float((unsigned)u); }
__device__ __forceinline__ float hi32(uint64_t u) { return __uint_as_float((unsigned)(u >> 32)); }

// Vertical accumulation body; RCHK adds per-row bounds predication.
template<bool RCHK>
__device__ __forceinline__ void vbody(const float* __restrict__ p1,
                                      const float* __restrict__ p2,
                                      int gy_first,
                                      uint64_t (&a01)[8], uint64_t (&asp)[8],
                                      const uint64_t (&Wb)[6])
{
    #pragma unroll
    for (int e = 0; e < 18; e++) {
        float x, y;
        if (RCHK) {
            bool ok = (unsigned)(gy_first + e) < (unsigned)IMG;
            x = ok ? __ldg(p1 + e * IMG) : 0.0f;
            y = ok ? __ldg(p2 + e * IMG) : 0.0f;
        } else {
            x = __ldg(p1 + e * IMG);
            y = __ldg(p2 + e * IMG);
        }
        uint64_t xy = pack2(x, y);
        uint64_t sp = pack2(fmaf(y, y, x * x), x * y);
        #pragma unroll
        for (int o = 0; o < 8; o++) {
            const int d = e - o;
            if (d >= 0 && d < 11) {
                const int wi = (d < 6) ? d : 10 - d;
                f2fma(a01[o], Wb[wi], xy);
                f2fma(asp[o], Wb[wi], sp);
            }
        }
    }
}

// Horizontal blur strip of LEN output cols + pointwise SSIM.
template<int LEN>
__device__ __forceinline__ float hstrip(const ulonglong2* __restrict__ S, int row, int cs,
                                        const uint64_t (&Wb)[6])
{
    const ulonglong2* p = S + row * VP + cs;
    uint64_t b01[LEN], bsp[LEN];
    #pragma unroll
    for (int o = 0; o < LEN; o++) { b01[o] = 0ull; bsp[o] = 0ull; }

    #pragma unroll
    for (int e = 0; e < LEN + 10; e++) {
        ulonglong2 f = p[e];                 // one LDS.128: both planes
        #pragma unroll
        for (int o = 0; o < LEN; o++) {
            const int d = e - o;
            if (d >= 0 && d < 11) {
                const int wi = (d < 6) ? d : 10 - d;
                f2fma(b01[o], Wb[wi], f.x);
                f2fma(bsp[o], Wb[wi], f.y);
            }
        }
    }

    const float C1 = 1e-4f, C2 = 9e-4f;
    float acc = 0.f;
    #pragma unroll
    for (int o = 0; o < LEN; o++) {
        float mu1 = lo32(b01[o]), mu2 = hi32(b01[o]);
        float Sb  = lo32(bsp[o]), Pb  = hi32(bsp[o]);
        float mu1sq = mu1 * mu1;
        float musum = fmaf(mu2, mu2, mu1sq);
        float mu12  = mu1 * mu2;
        float sg12  = Pb - mu12;
        float sgsum = Sb - musum;
        float num = fmaf(2.0f, mu12, C1) * fmaf(2.0f, sg12, C2);
        float den = (musum + C1) * (sgsum + C2);
        acc += __fdividef(num, den);
    }
    return acc;
}

__global__ __launch_bounds__(NT, 8)
void ssim_kernel(const float* __restrict__ img1,
                 const float* __restrict__ img2,
                 float* __restrict__ out)
{
    extern __shared__ ulonglong2 S[];   // [TY][VP] interleaved (v01, vsp)
    const int tid = threadIdx.x;
    const int bz  = blockIdx.z;
    const float* ib1 = img1 + (size_t)bz * IMG * IMG;
    const float* ib2 = img2 + (size_t)bz * IMG * IMG;
    const int gx0 = blockIdx.x * TX - 5;
    const int gy0 = blockIdx.y * TY - 5;

    const uint64_t Wb[6] = { bc(W0f), bc(W1f), bc(W2f), bc(W3f), bc(W4f), bc(W5f) };

    // ---- pass V: vertical blur straight from gmem (lane = column, coalesced) ----
    // 148 strips = 74 cols x 2 row-strips of 8 outputs.
    if (tid < COLS * 2) {
        int s = (tid >= COLS) ? 1 : 0;
        int c = tid - s * COLS;           // 0..73
        int gx = gx0 + c;
        int r0 = s * 8;

        uint64_t a01[8], asp[8];
        #pragma unroll
        for (int o = 0; o < 8; o++) { a01[o] = 0ull; asp[o] = 0ull; }

        const bool colsafe = (gx0 >= 0) & (gx0 + COLS - 1 < IMG);   // block-uniform
        if (colsafe | ((unsigned)gx < (unsigned)IMG)) {
            const int gy_first = gy0 + r0;
            const float* p1 = ib1 + (size_t)gy_first * IMG + gx;
            const float* p2 = ib2 + (size_t)gy_first * IMG + gx;
            const bool rowsafe = (gy0 >= 0) & (gy0 + TY + 9 < IMG); // block-uniform
            if (rowsafe) vbody<false>(p1, p2, gy_first, a01, asp, Wb);
            else         vbody<true >(p1, p2, gy_first, a01, asp, Wb);
        }
        #pragma unroll
        for (int o = 0; o < 8; o++)
            S[(r0 + o) * VP + c] = make_ulonglong2(a01[o], asp[o]);  // STS.128
    }
    __syncthreads();

    // ---- pass H: 192 strips = 16 rows x 12 groups; LENs {6,6,6,6,5x8} ----
    // warp-uniform: two groups per warp share the same LEN.
    float acc;
    {
        const int row = tid & 15;
        const int g   = tid >> 4;         // 0..11
        if (g < 4) acc = hstrip<6>(S, row, g * 6, Wb);
        else       acc = hstrip<5>(S, row, 24 + (g - 4) * 5, Wb);
    }

    // ---- block reduction ----
    #pragma unroll
    for (int off = 16; off > 0; off >>= 1)
        acc += __shfl_xor_sync(0xFFFFFFFFu, acc, off);

    __shared__ float warpsum[NT / 32];
    if ((tid & 31) == 0) warpsum[tid >> 5] = acc;
    __syncthreads();

    __shared__ bool is_last;
    if (tid == 0) {
        float s = 0.f;
        #pragma unroll
        for (int i = 0; i < NT / 32; i++) s += warpsum[i];
        int bid = blockIdx.x + GXB * (blockIdx.y + GYB * bz);
        g_partials[bid] = s;
        __threadfence();
        unsigned prev = atomicAdd(&g_sync, 1u);
        is_last = (prev == NBLOCKS - 1);
    }
    __syncthreads();

    // ---- last block: deterministic final reduction ----
    // 192 = 64*3: fold to 64, then power-of-two tree 64 -> 1.
    if (is_last) {
        __threadfence();
        __shared__ double sd[NT];
        double s = 0.0;
        for (int k = tid; k < NBLOCKS; k += NT)
            s += (double)g_partials[k];
        sd[tid] = s;
        __syncthreads();
        if (tid < 64) sd[tid] += sd[tid + 64] + sd[tid + 128];
        __syncthreads();
        #pragma unroll
        for (int st = 32; st > 0; st >>= 1) {
            if (tid < st) sd[tid] += sd[tid + st];
            __syncthreads();
        }
        if (tid == 0) {
            const double N = 16.0 * 3.0 * 512.0 * 512.0;
            out[0] = (float)(1.0 - sd[0] / N);
            g_sync = 0;     // reset for next graph replay
        }
    }
}

extern "C" void kernel_launch(void* const* d_in, const int* in_sizes, int n_in,
                              void* d_out, int out_size)
{
    const float* img1 = (const float*)d_in[0];
    const float* img2 = (const float*)d_in[1];
    float* out = (float*)d_out;

    cudaFuncSetAttribute(ssim_kernel,
                         cudaFuncAttributeMaxDynamicSharedMemorySize, SMEM_BYTES);

    dim3 grid(GXB, GYB, NIMG);
    ssim_kernel<<<grid, NT, SMEM_BYTES>>>(img1, img2, out);
}

// round 16
// speedup vs baseline: 1.3943x; 1.3943x over previous
#include <cuda_runtime.h>
#include <cstdint>

// SSIM loss: fused separable 11x11 Gaussian, V-first, interleaved smem planes.
// Channels: blur(x), blur(y), blur(x^2+y^2), blur(xy) -> two packed f32x2.
// 64x16 tiles, NT=128, 8 CTAs/SM; H = 8 x LEN8 strips (max ILP), V looped.

#define IMG     512
#define NIMG    48
#define TX      64
#define TY      16
#define COLS    74              // TX + 10
#define VP      75              // V plane row stride in ulonglong2 elements
#define NT      128             // 4 warps
#define GXB     8
#define GYB     32
#define NBLOCKS (GXB*GYB*NIMG)  // 12288
#define SMEM_BYTES (TY*VP*16)   // 19200

#define W0f 0.00102838f
#define W1f 0.00759876f
#define W2f 0.03600077f
#define W3f 0.10936070f
#define W4f 0.21300554f
#define W5f 0.26601173f

__device__ float    g_partials[NBLOCKS];
__device__ unsigned g_sync = 0;

__device__ __forceinline__ uint64_t bc(float w) {
    unsigned u = __float_as_uint(w);
    return ((uint64_t)u << 32) | u;
}
__device__ __forceinline__ void f2fma(uint64_t& d, uint64_t a, uint64_t b) {
    asm("fma.rn.f32x2 %0,%1,%2,%0;" : "+l"(d) : "l"(a), "l"(b));
}
__device__ __forceinline__ uint64_t pack2(float lo, float hi) {
    uint64_t r; asm("mov.b64 %0,{%1,%2};" : "=l"(r) : "r"(__float_as_uint(lo)), "r"(__float_as_uint(hi)));
    return r;
}
__device__ __forceinline__ float lo32(uint64_t u) { return __uint_as_float((unsigned)u); }
__device__ __forceinline__ float hi32(uint64_t u) { return __uint_as_float((unsigned)(u >> 32)); }

// Vertical accumulation body; RCHK adds per-row bounds predication.
template<bool RCHK>
__device__ __forceinline__ void vbody(const float* __restrict__ p1,
                                      const float* __restrict__ p2,
                                      int gy_first,
                                      uint64_t (&a01)[8], uint64_t (&asp)[8],
                                      const uint64_t (&Wb)[6])
{
    #pragma unroll
    for (int e = 0; e < 18; e++) {
        float x, y;
        if (RCHK) {
            bool ok = (unsigned)(gy_first + e) < (unsigned)IMG;
            x = ok ? __ldg(p1 + e * IMG) : 0.0f;
            y = ok ? __ldg(p2 + e * IMG) : 0.0f;
        } else {
            x = __ldg(p1 + e * IMG);
            y = __ldg(p2 + e * IMG);
        }
        uint64_t xy = pack2(x, y);
        uint64_t sp = pack2(fmaf(y, y, x * x), x * y);
        #pragma unroll
        for (int o = 0; o < 8; o++) {
            const int d = e - o;
            if (d >= 0 && d < 11) {
                const int wi = (d < 6) ? d : 10 - d;
                f2fma(a01[o], Wb[wi], xy);
                f2fma(asp[o], Wb[wi], sp);
            }
        }
    }
}

// One V strip: column c, output rows r0..r0+7 of the tile.
__device__ __forceinline__ void vstrip_do(const float* __restrict__ ib1,
                                          const float* __restrict__ ib2,
                                          ulonglong2* __restrict__ S,
                                          int gx0, int gy0, int c, int r0,
                                          const uint64_t (&Wb)[6])
{
    int gx = gx0 + c;
    uint64_t a01[8], asp[8];
    #pragma unroll
    for (int o = 0; o < 8; o++) { a01[o] = 0ull; asp[o] = 0ull; }

    const bool colsafe = (gx0 >= 0) & (gx0 + COLS - 1 < IMG);   // block-uniform
    if (colsafe | ((unsigned)gx < (unsigned)IMG)) {
        const int gy_first = gy0 + r0;
        const float* p1 = ib1 + (size_t)gy_first * IMG + gx;
        const float* p2 = ib2 + (size_t)gy_first * IMG + gx;
        const bool rowsafe = (gy0 >= 0) & (gy0 + TY + 9 < IMG); // block-uniform
        if (rowsafe) vbody<false>(p1, p2, gy_first, a01, asp, Wb);
        else         vbody<true >(p1, p2, gy_first, a01, asp, Wb);
    }
    #pragma unroll
    for (int o = 0; o < 8; o++)
        S[(r0 + o) * VP + c] = make_ulonglong2(a01[o], asp[o]);  // STS.128
}

// Horizontal blur strip of LEN output cols + pointwise SSIM.
template<int LEN>
__device__ __forceinline__ float hstrip(const ulonglong2* __restrict__ S, int row, int cs,
                                        const uint64_t (&Wb)[6])
{
    const ulonglong2* p = S + row * VP + cs;
    uint64_t b01[LEN], bsp[LEN];
    #pragma unroll
    for (int o = 0; o < LEN; o++) { b01[o] = 0ull; bsp[o] = 0ull; }

    #pragma unroll
    for (int e = 0; e < LEN + 10; e++) {
        ulonglong2 f = p[e];                 // one LDS.128: both planes
        #pragma unroll
        for (int o = 0; o < LEN; o++) {
            const int d = e - o;
            if (d >= 0 && d < 11) {
                const int wi = (d < 6) ? d : 10 - d;
                f2fma(b01[o], Wb[wi], f.x);
                f2fma(bsp[o], Wb[wi], f.y);
            }
        }
    }

    const float C1 = 1e-4f, C2 = 9e-4f;
    float acc = 0.f;
    #pragma unroll
    for (int o = 0; o < LEN; o++) {
        float mu1 = lo32(b01[o]), mu2 = hi32(b01[o]);
        float Sb  = lo32(bsp[o]), Pb  = hi32(bsp[o]);
        float mu1sq = mu1 * mu1;
        float musum = fmaf(mu2, mu2, mu1sq);
        float mu12  = mu1 * mu2;
        float sg12  = Pb - mu12;
        float sgsum = Sb - musum;
        float num = fmaf(2.0f, mu12, C1) * fmaf(2.0f, sg12, C2);
        float den = (musum + C1) * (sgsum + C2);
        acc += __fdividef(num, den);
    }
    return acc;
}

__global__ __launch_bounds__(NT, 8)
void ssim_kernel(const float* __restrict__ img1,
                 const float* __restrict__ img2,
                 float* __restrict__ out)
{
    extern __shared__ ulonglong2 S[];   // [TY][VP] interleaved (v01, vsp)
    const int tid = threadIdx.x;
    const int bz  = blockIdx.z;
    const float* ib1 = img1 + (size_t)bz * IMG * IMG;
    const float* ib2 = img2 + (size_t)bz * IMG * IMG;
    const int gx0 = blockIdx.x * TX - 5;
    const int gy0 = blockIdx.y * TY - 5;

    const uint64_t Wb[6] = { bc(W0f), bc(W1f), bc(W2f), bc(W3f), bc(W4f), bc(W5f) };

    // ---- pass V: 148 strips (74 cols x 2 row-strips) over 128 threads ----
    {
        int s = (tid >= COLS) ? 1 : 0;
        int c = tid - s * COLS;
        vstrip_do(ib1, ib2, S, gx0, gy0, c, s * 8, Wb);
        if (tid < 148 - NT)                 // threads 0..19: second strip
            vstrip_do(ib1, ib2, S, gx0, gy0, (tid + NT) - COLS, 8, Wb);
    }
    __syncthreads();

    // ---- pass H: 128 strips = 16 rows x 8 groups of LEN8 (100% util) ----
    float acc;
    {
        const int row = tid & 15;
        const int g   = tid >> 4;         // 0..7
        acc = hstrip<8>(S, row, g * 8, Wb);
    }

    // ---- block reduction ----
    #pragma unroll
    for (int off = 16; off > 0; off >>= 1)
        acc += __shfl_xor_sync(0xFFFFFFFFu, acc, off);

    __shared__ float warpsum[NT / 32];
    if ((tid & 31) == 0) warpsum[tid >> 5] = acc;
    __syncthreads();

    __shared__ bool is_last;
    if (tid == 0) {
        float s = 0.f;
        #pragma unroll
        for (int i = 0; i < NT / 32; i++) s += warpsum[i];
        int bid = blockIdx.x + GXB * (blockIdx.y + GYB * bz);
        g_partials[bid] = s;
        __threadfence();
        unsigned prev = atomicAdd(&g_sync, 1u);
        is_last = (prev == NBLOCKS - 1);
    }
    __syncthreads();

    // ---- last block: deterministic final reduction (NT=128, power of two) ----
    if (is_last) {
        __threadfence();
        __shared__ double sd[NT];
        double s = 0.0;
        for (int k = tid; k < NBLOCKS; k += NT)
            s += (double)g_partials[k];
        sd[tid] = s;
        __syncthreads();
        #pragma unroll
        for (int st = 64; st > 0; st >>= 1) {
            if (tid < st) sd[tid] += sd[tid + st];
            __syncthreads();
        }
        if (tid == 0) {
            const double N = 16.0 * 3.0 * 512.0 * 512.0;
            out[0] = (float)(1.0 - sd[0] / N);
            g_sync = 0;     // reset for next graph replay
        }
    }
}

extern "C" void kernel_launch(void* const* d_in, const int* in_sizes, int n_in,
                              void* d_out, int out_size)
{
    const float* img1 = (const float*)d_in[0];
    const float* img2 = (const float*)d_in[1];
    float* out = (float*)d_out;

    cudaFuncSetAttribute(ssim_kernel,
                         cudaFuncAttributeMaxDynamicSharedMemorySize, SMEM_BYTES);

    dim3 grid(GXB, GYB, NIMG);
    ssim_kernel<<<grid, NT, SMEM_BYTES>>>(img1, img2, out);
}